// round 8
// baseline (speedup 1.0000x reference)
#include <cuda_runtime.h>
#include <cstdint>
#include <math.h>

// Problem constants
#define Bb   8
#define Tt   2048
#define Dd   1024
#define Hh   8
#define Cc   64
#define DVv  128
#define Mm   (Bb*Tt)
#define PSTR  768
#define CH   16

// ---------------- scratch -------------------------------------------------
__device__ float g_xn  [(size_t)Mm*Dd];
__device__ float g_wall[(size_t)PSTR*Dd];
__device__ float g_hwq [(size_t)512*Cc];
__device__ float g_hwv [(size_t)1024*Cc];
__device__ float g_proj[(size_t)Mm*PSTR];     // qlat|kn|vlat|alpha(sigmoided)
__device__ float g_q   [(size_t)Mm*512];
__device__ float g_v   [(size_t)Mm*1024];
__device__ float g_o   [(size_t)Mm*Dd];

// ---------------- 1. LayerNorm -------------------------------------------
__global__ __launch_bounds__(256)
void ln_kernel(const float* __restrict__ x, const float* __restrict__ gamma,
               const float* __restrict__ beta)
{
    int row = blockIdx.x;
    int tid = threadIdx.x;
    const float4* xr = (const float4*)(x + (size_t)row*Dd);
    float4 v = xr[tid];
    float s  = v.x + v.y + v.z + v.w;
    float s2 = v.x*v.x + v.y*v.y + v.z*v.z + v.w*v.w;
    #pragma unroll
    for (int o = 16; o > 0; o >>= 1) {
        s  += __shfl_xor_sync(0xffffffffu, s,  o);
        s2 += __shfl_xor_sync(0xffffffffu, s2, o);
    }
    __shared__ float r1[8], r2[8];
    int w = tid >> 5, l = tid & 31;
    if (l == 0) { r1[w] = s; r2[w] = s2; }
    __syncthreads();
    s = 0.f; s2 = 0.f;
    #pragma unroll
    for (int i = 0; i < 8; i++) { s += r1[i]; s2 += r2[i]; }
    float mu  = s * (1.f/Dd);
    float var = s2 * (1.f/Dd) - mu*mu;
    float inv = rsqrtf(var + 1e-5f);
    float4 g  = ((const float4*)gamma)[tid];
    float4 be = ((const float4*)beta)[tid];
    float4 o;
    o.x = (v.x - mu)*inv*g.x + be.x;
    o.y = (v.y - mu)*inv*g.y + be.y;
    o.z = (v.z - mu)*inv*g.z + be.z;
    o.w = (v.w - mu)*inv*g.w + be.w;
    ((float4*)(g_xn + (size_t)row*Dd))[tid] = o;
}

// ---------------- 2. weight prep ------------------------------------------
#define WALL_ELEMS (PSTR*Dd)
#define HWQ_ELEMS  (512*Cc)
#define HWV_ELEMS  (1024*Cc)
__global__ void prep_weights(const float* __restrict__ Wq, const float* __restrict__ Wk,
                             const float* __restrict__ Wv, const float* __restrict__ Wa,
                             const float* __restrict__ Qc, const float* __restrict__ Vc)
{
    int i = blockIdx.x * blockDim.x + threadIdx.x;
    if (i < WALL_ELEMS) {
        int row = i >> 10, col = i & 1023;
        float val;
        if      (row <  64) val = Wq[(size_t)row       *1024 + col];
        else if (row < 128) val = Wk[(size_t)(row- 64) *1024 + col];
        else if (row < 192) val = Wv[(size_t)(row-128) *1024 + col];
        else if (row < 704) val = Wa[(size_t)(row-192) *1024 + col];
        else                val = 0.f;
        g_wall[i] = val;
    } else if (i < WALL_ELEMS + HWQ_ELEMS) {
        int j = i - WALL_ELEMS;
        int n = j >> 6, c = j & 63;
        int h = n >> 6, e = n & 63;
        g_hwq[j] = Qc[(size_t)h*Cc*Cc + (size_t)c*Cc + e];
    } else if (i < WALL_ELEMS + HWQ_ELEMS + HWV_ELEMS) {
        int j = i - WALL_ELEMS - HWQ_ELEMS;
        int n = j >> 6, c = j & 63;
        int h = n >> 7, d = n & 127;
        g_hwv[j] = Vc[(size_t)h*Cc*DVv + (size_t)c*DVv + d];
    }
}

// ---------------- 3. TF32 GEMM, 64x64 warp tile ---------------------------
// Y[M,N] = A[M,K] @ W[N,K]^T. 128 threads, 2x2 warps of 64x64.
// mode 0: plain; 1: += resid; 2: proj epilogue (knorm cols 64-127, sigmoid 192-703)
__device__ __forceinline__ uint32_t f2tf32(float f) {
    uint32_t u;
    asm volatile("cvt.rna.tf32.f32 %0, %1;" : "=r"(u) : "f"(f));
    return u;
}
__device__ __forceinline__ void mma_tf32(float c[4], const uint32_t a[4], const uint32_t b[2]) {
    asm volatile(
        "mma.sync.aligned.m16n8k8.row.col.f32.tf32.tf32.f32 "
        "{%0,%1,%2,%3}, {%4,%5,%6,%7}, {%8,%9}, {%0,%1,%2,%3};\n"
        : "+f"(c[0]), "+f"(c[1]), "+f"(c[2]), "+f"(c[3])
        : "r"(a[0]), "r"(a[1]), "r"(a[2]), "r"(a[3]), "r"(b[0]), "r"(b[1]));
}

__global__ __launch_bounds__(128, 2)
void gemm_tf32(int K, int lda, int ldy, int mode,
               const float* __restrict__ A,
               const float* __restrict__ W,
               float* __restrict__ Y,
               const float* __restrict__ resid,
               const float* __restrict__ bias)
{
    __shared__ uint32_t As[2][128*20];
    __shared__ uint32_t Bs[2][128*20];

    int tid  = threadIdx.x;
    int lane = tid & 31, warp = tid >> 5;
    int wm = warp & 1, wn = warp >> 1;       // 2x2 warp grid
    int g  = lane >> 2, tig = lane & 3;
    int row0 = blockIdx.y * 128;
    int col0 = blockIdx.x * 128;

    int lrow = tid >> 1;
    int kb   = (tid & 1) * 8;
    const float* Ap = A + (size_t)(row0 + lrow) * lda + kb;
    const float* Bp = W + (size_t)(col0 + lrow) * K + kb;

    float acc[4][8][4];
    #pragma unroll
    for (int i = 0; i < 4; i++)
        #pragma unroll
        for (int j = 0; j < 8; j++)
            #pragma unroll
            for (int e = 0; e < 4; e++) acc[i][j][e] = 0.f;

    {
        float4 a00 = *(const float4*)(Ap);
        float4 a01 = *(const float4*)(Ap + 4);
        float4 a10 = *(const float4*)(Ap + (size_t)64*lda);
        float4 a11 = *(const float4*)(Ap + (size_t)64*lda + 4);
        float4 b00 = *(const float4*)(Bp);
        float4 b01 = *(const float4*)(Bp + 4);
        float4 b10 = *(const float4*)(Bp + (size_t)64*K);
        float4 b11 = *(const float4*)(Bp + (size_t)64*K + 4);
        *(uint4*)&As[0][lrow*20 + kb]          = make_uint4(f2tf32(a00.x), f2tf32(a00.y), f2tf32(a00.z), f2tf32(a00.w));
        *(uint4*)&As[0][lrow*20 + kb + 4]      = make_uint4(f2tf32(a01.x), f2tf32(a01.y), f2tf32(a01.z), f2tf32(a01.w));
        *(uint4*)&As[0][(lrow+64)*20 + kb]     = make_uint4(f2tf32(a10.x), f2tf32(a10.y), f2tf32(a10.z), f2tf32(a10.w));
        *(uint4*)&As[0][(lrow+64)*20 + kb + 4] = make_uint4(f2tf32(a11.x), f2tf32(a11.y), f2tf32(a11.z), f2tf32(a11.w));
        *(uint4*)&Bs[0][lrow*20 + kb]          = make_uint4(f2tf32(b00.x), f2tf32(b00.y), f2tf32(b00.z), f2tf32(b00.w));
        *(uint4*)&Bs[0][lrow*20 + kb + 4]      = make_uint4(f2tf32(b01.x), f2tf32(b01.y), f2tf32(b01.z), f2tf32(b01.w));
        *(uint4*)&Bs[0][(lrow+64)*20 + kb]     = make_uint4(f2tf32(b10.x), f2tf32(b10.y), f2tf32(b10.z), f2tf32(b10.w));
        *(uint4*)&Bs[0][(lrow+64)*20 + kb + 4] = make_uint4(f2tf32(b11.x), f2tf32(b11.y), f2tf32(b11.z), f2tf32(b11.w));
    }
    __syncthreads();

    int buf = 0;
    for (int k0 = 0; k0 < K; k0 += 16) {
        float4 pa00, pa01, pa10, pa11, pb00, pb01, pb10, pb11;
        bool more = (k0 + 16) < K;
        if (more) {
            const float* Ak = Ap + k0 + 16;
            const float* Bk = Bp + k0 + 16;
            pa00 = *(const float4*)(Ak);
            pa01 = *(const float4*)(Ak + 4);
            pa10 = *(const float4*)(Ak + (size_t)64*lda);
            pa11 = *(const float4*)(Ak + (size_t)64*lda + 4);
            pb00 = *(const float4*)(Bk);
            pb01 = *(const float4*)(Bk + 4);
            pb10 = *(const float4*)(Bk + (size_t)64*K);
            pb11 = *(const float4*)(Bk + (size_t)64*K + 4);
        }

        const uint32_t* Ab  = As[buf];
        const uint32_t* Bb_ = Bs[buf];
        #pragma unroll
        for (int ks = 0; ks < 16; ks += 8) {
            uint32_t af[4][4], bf[8][2];
            #pragma unroll
            for (int i = 0; i < 4; i++) {
                int base = (wm*64 + i*16 + g)*20 + ks + tig;
                af[i][0] = Ab[base];
                af[i][1] = Ab[base + 8*20];
                af[i][2] = Ab[base + 4];
                af[i][3] = Ab[base + 8*20 + 4];
            }
            #pragma unroll
            for (int j = 0; j < 8; j++) {
                int base = (wn*64 + j*8 + g)*20 + ks + tig;
                bf[j][0] = Bb_[base];
                bf[j][1] = Bb_[base + 4];
            }
            #pragma unroll
            for (int i = 0; i < 4; i++)
                #pragma unroll
                for (int j = 0; j < 8; j++)
                    mma_tf32(acc[i][j], af[i], bf[j]);
        }

        if (more) {
            int nb = buf ^ 1;
            *(uint4*)&As[nb][lrow*20 + kb]          = make_uint4(f2tf32(pa00.x), f2tf32(pa00.y), f2tf32(pa00.z), f2tf32(pa00.w));
            *(uint4*)&As[nb][lrow*20 + kb + 4]      = make_uint4(f2tf32(pa01.x), f2tf32(pa01.y), f2tf32(pa01.z), f2tf32(pa01.w));
            *(uint4*)&As[nb][(lrow+64)*20 + kb]     = make_uint4(f2tf32(pa10.x), f2tf32(pa10.y), f2tf32(pa10.z), f2tf32(pa10.w));
            *(uint4*)&As[nb][(lrow+64)*20 + kb + 4] = make_uint4(f2tf32(pa11.x), f2tf32(pa11.y), f2tf32(pa11.z), f2tf32(pa11.w));
            *(uint4*)&Bs[nb][lrow*20 + kb]          = make_uint4(f2tf32(pb00.x), f2tf32(pb00.y), f2tf32(pb00.z), f2tf32(pb00.w));
            *(uint4*)&Bs[nb][lrow*20 + kb + 4]      = make_uint4(f2tf32(pb01.x), f2tf32(pb01.y), f2tf32(pb01.z), f2tf32(pb01.w));
            *(uint4*)&Bs[nb][(lrow+64)*20 + kb]     = make_uint4(f2tf32(pb10.x), f2tf32(pb10.y), f2tf32(pb10.z), f2tf32(pb10.w));
            *(uint4*)&Bs[nb][(lrow+64)*20 + kb + 4] = make_uint4(f2tf32(pb11.x), f2tf32(pb11.y), f2tf32(pb11.z), f2tf32(pb11.w));
            __syncthreads();
            buf = nb;
        }
    }

    bool knorm_warp = (mode == 2) && (col0 + wn*64 == 64);
    #pragma unroll
    for (int i = 0; i < 4; i++) {
        #pragma unroll
        for (int half = 0; half < 2; half++) {
            int m = row0 + wm*64 + i*16 + g + half*8;
            float scale = 1.f;
            if (knorm_warp) {
                float s = 0.f;
                #pragma unroll
                for (int j = 0; j < 8; j++) {
                    float e0 = acc[i][j][half*2], e1 = acc[i][j][half*2+1];
                    s = fmaf(e0, e0, s); s = fmaf(e1, e1, s);
                }
                s += __shfl_xor_sync(0xffffffffu, s, 1);
                s += __shfl_xor_sync(0xffffffffu, s, 2);
                scale = 1.f / fmaxf(sqrtf(s), 1e-12f);
            }
            #pragma unroll
            for (int j = 0; j < 8; j++) {
                int n0 = col0 + wn*64 + j*8 + tig*2;
                float2 val = make_float2(acc[i][j][half*2], acc[i][j][half*2+1]);
                if (mode == 1) {
                    const float2 r = *(const float2*)(resid + (size_t)m*ldy + n0);
                    val.x += r.x; val.y += r.y;
                } else if (mode == 2) {
                    if (knorm_warp) {
                        val.x *= scale; val.y *= scale;
                    } else if (n0 >= 192 && n0 < 704) {
                        float2 bb = *(const float2*)(bias + n0 - 192);
                        val.x = 1.f / (1.f + expf(-(val.x + bb.x)));
                        val.y = 1.f / (1.f + expf(-(val.y + bb.y)));
                    }
                }
                *(float2*)(Y + (size_t)m*ldy + n0) = val;
            }
        }
    }
}

// ---------------- 4. recurrent scan (f32x2 packed, chunked) ----------------
// Block = (b,h,vhalf). 256 threads: vi = tid>>2 (64 v), cg = tid&3 (16 c each,
// held as 8 c-pairs in f32x2). a/k/q pairs load directly as 16B ulonglong2.
#define MUL2(d, a, b)    asm("mul.rn.f32x2 %0, %1, %2;" : "=l"(d) : "l"(a), "l"(b))
#define FMA2(d, a, b, c) asm("fma.rn.f32x2 %0, %1, %2, %3;" : "=l"(d) : "l"(a), "l"(b), "l"(c))

__global__ __launch_bounds__(256)
void scan_kernel()
{
    int blk   = blockIdx.x;
    int bh    = blk >> 1;
    int vhalf = blk & 1;
    int b = bh >> 3, h = bh & 7;
    int tid = threadIdx.x;
    int vi  = tid >> 2;      // 0..63
    int cg  = tid & 3;       // 0..3 (16 c's each)
    const float* qp = g_q + (size_t)(b*Tt)*512 + h*64;
    const float* vp = g_v + (size_t)(b*Tt)*1024 + h*128 + vhalf*64;
    const float* pp = g_proj + (size_t)b * Tt * PSTR;
    float* op = g_o + (size_t)b * Tt * Dd + h*DVv + vhalf*64 + vi;

    // chunk loader: flat float4 index f = i*256 + tid; q4=f&15, s=(f>>4)&3, r=f>>6
    const float* lsrc[4];
    size_t ladv[4];
    int ldst[4];
    #pragma unroll
    for (int i = 0; i < 4; i++) {
        int f = i * 256 + tid;
        int lq4 = f & 15, ls = (f >> 4) & 3, lr = f >> 6;
        switch (ls) {
            case 0:  lsrc[i] = pp + (size_t)lr*PSTR + 192 + h*64 + lq4*4; ladv[i] = (size_t)CH*PSTR; break;
            case 1:  lsrc[i] = pp + (size_t)lr*PSTR + 64 + lq4*4;         ladv[i] = (size_t)CH*PSTR; break;
            case 2:  lsrc[i] = qp + (size_t)lr*512 + lq4*4;               ladv[i] = (size_t)CH*512;  break;
            default: lsrc[i] = vp + (size_t)lr*1024 + lq4*4;              ladv[i] = (size_t)CH*1024; break;
        }
        ldst[i] = (lr*4 + ls)*64 + lq4*4;
    }

    __shared__ __align__(16) float sh[2][CH*256];
    unsigned long long S[8];
    #pragma unroll
    for (int i = 0; i < 8; i++) S[i] = 0ull;   // {0.f, 0.f}

    #pragma unroll
    for (int i = 0; i < 4; i++)
        *(float4*)&sh[0][ldst[i]] = *(const float4*)lsrc[i];
    __syncthreads();

    int buf = 0;
    for (int c = 0; c < Tt/CH; c++) {
        float4 pf[4];
        bool more = (c + 1) < (Tt/CH);
        if (more) {
            #pragma unroll
            for (int i = 0; i < 4; i++)
                pf[i] = *(const float4*)(lsrc[i] + (size_t)(c+1)*ladv[i]);
        }
        const float* cb = sh[buf];
        #pragma unroll 4
        for (int r = 0; r < CH; r++) {
            const float* base = cb + r*256;
            // load 16 c's of a,k,q as 8 f32x2 pairs each (4 x 16B loads per segment)
            unsigned long long a2[8], k2[8], q2[8];
            #pragma unroll
            for (int jj = 0; jj < 4; jj++) {
                ulonglong2 t;
                t = *(const ulonglong2*)(base +       cg*16 + jj*4); a2[2*jj] = t.x; a2[2*jj+1] = t.y;
                t = *(const ulonglong2*)(base +  64 + cg*16 + jj*4); k2[2*jj] = t.x; k2[2*jj+1] = t.y;
                t = *(const ulonglong2*)(base + 128 + cg*16 + jj*4); q2[2*jj] = t.x; q2[2*jj+1] = t.y;
            }
            float vt = base[192 + vi];
            unsigned long long vt2;
            {
                uint32_t u = __float_as_uint(vt);
                asm("mov.b64 %0, {%1, %1};" : "=l"(vt2) : "r"(u));
            }
            unsigned long long acc2 = 0ull;
            #pragma unroll
            for (int j = 0; j < 8; j++) {
                unsigned long long kv;
                MUL2(kv, k2[j], vt2);
                FMA2(S[j], a2[j], S[j], kv);
                FMA2(acc2, q2[j], S[j], acc2);
            }
            uint32_t alo, ahi;
            asm("mov.b64 {%0, %1}, %2;" : "=r"(alo), "=r"(ahi) : "l"(acc2));
            float acc = __uint_as_float(alo) + __uint_as_float(ahi);
            acc += __shfl_xor_sync(0xffffffffu, acc, 1);
            acc += __shfl_xor_sync(0xffffffffu, acc, 2);
            if (cg == 0) op[(size_t)(c*CH + r) * Dd] = acc;
        }
        if (more) {
            int nb = buf ^ 1;
            #pragma unroll
            for (int i = 0; i < 4; i++)
                *(float4*)&sh[nb][ldst[i]] = pf[i];
            __syncthreads();
            buf = nb;
        }
    }
}

// ---------------- launch ---------------------------------------------------
extern "C" void kernel_launch(void* const* d_in, const int* in_sizes, int n_in,
                              void* d_out, int out_size)
{
    const float* x     = (const float*)d_in[0];
    const float* Wq    = (const float*)d_in[1];
    const float* Wk    = (const float*)d_in[2];
    const float* Wv    = (const float*)d_in[3];
    const float* Qc    = (const float*)d_in[4];
    const float* Vc    = (const float*)d_in[5];
    const float* Wa_w  = (const float*)d_in[6];
    const float* Wa_b  = (const float*)d_in[7];
    const float* Wo    = (const float*)d_in[8];
    const float* gamma = (const float*)d_in[9];
    const float* beta  = (const float*)d_in[10];
    float* out = (float*)d_out;

    float *xn, *wall, *hwq, *hwv, *proj, *q, *v, *o;
    cudaGetSymbolAddress((void**)&xn,   g_xn);
    cudaGetSymbolAddress((void**)&wall, g_wall);
    cudaGetSymbolAddress((void**)&hwq,  g_hwq);
    cudaGetSymbolAddress((void**)&hwv,  g_hwv);
    cudaGetSymbolAddress((void**)&proj, g_proj);
    cudaGetSymbolAddress((void**)&q,    g_q);
    cudaGetSymbolAddress((void**)&v,    g_v);
    cudaGetSymbolAddress((void**)&o,    g_o);

    int prep_total = WALL_ELEMS + HWQ_ELEMS + HWV_ELEMS;

    // 1. layernorm
    ln_kernel<<<Mm, 256>>>(x, gamma, beta);
    // 2. weight prep
    prep_weights<<<(prep_total + 255)/256, 256>>>(Wq, Wk, Wv, Wa_w, Qc, Vc);
    // 3. projection GEMM + fused epi (knorm + sigmoid)
    gemm_tf32<<<dim3(PSTR/128, Mm/128), 128>>>(Dd, Dd, PSTR, 2, xn, wall, proj, nullptr, Wa_b);
    // 4. head Q GEMM: q[16384,512] = q_lat @ hwq^T (K=64)
    gemm_tf32<<<dim3(512/128, Mm/128), 128>>>(Cc, PSTR, 512, 0, proj, hwq, q, nullptr, nullptr);
    // 5. head V GEMM: v[16384,1024] = v_lat @ hwv^T (K=64)
    gemm_tf32<<<dim3(1024/128, Mm/128), 128>>>(Cc, PSTR, 1024, 0, proj + 128, hwv, v, nullptr, nullptr);
    // 6. recurrent scan (f32x2 packed)
    scan_kernel<<<128, 256>>>();
    // 7. output GEMM + residual
    gemm_tf32<<<dim3(Dd/128, Mm/128), 128>>>(Dd, Dd, Dd, 1, o, Wo, out, x, nullptr);
}

// round 9
// speedup vs baseline: 1.2801x; 1.2801x over previous
#include <cuda_runtime.h>
#include <cstdint>
#include <math.h>

// Problem constants
#define Bb   8
#define Tt   2048
#define Dd   1024
#define Hh   8
#define Cc   64
#define DVv  128
#define Mm   (Bb*Tt)
#define PSTR  768
#define CH   16
#define QVS  1536          // merged q|v row stride

// ---------------- scratch -------------------------------------------------
__device__ float g_xn  [(size_t)Mm*Dd];
__device__ float g_wall[(size_t)PSTR*Dd];
__device__ float g_hw  [(size_t)QVS*Cc];      // rows 0-511: Qc concat; 512-1535: Vc concat
__device__ float g_proj[(size_t)Mm*PSTR];     // qlat|kn|vlat|alpha(sigmoided)
__device__ float g_qv  [(size_t)Mm*QVS];      // [m][ q(512) | v(1024) ]
__device__ float g_o   [(size_t)Mm*Dd];

// ---------------- 0. dummy (shifts ncu capture slot to the proj GEMM) -----
__global__ void dummy_k() {}

// ---------------- 1. LayerNorm -------------------------------------------
__global__ __launch_bounds__(256)
void ln_kernel(const float* __restrict__ x, const float* __restrict__ gamma,
               const float* __restrict__ beta)
{
    int row = blockIdx.x;
    int tid = threadIdx.x;
    const float4* xr = (const float4*)(x + (size_t)row*Dd);
    float4 v = xr[tid];
    float s  = v.x + v.y + v.z + v.w;
    float s2 = v.x*v.x + v.y*v.y + v.z*v.z + v.w*v.w;
    #pragma unroll
    for (int o = 16; o > 0; o >>= 1) {
        s  += __shfl_xor_sync(0xffffffffu, s,  o);
        s2 += __shfl_xor_sync(0xffffffffu, s2, o);
    }
    __shared__ float r1[8], r2[8];
    int w = tid >> 5, l = tid & 31;
    if (l == 0) { r1[w] = s; r2[w] = s2; }
    __syncthreads();
    s = 0.f; s2 = 0.f;
    #pragma unroll
    for (int i = 0; i < 8; i++) { s += r1[i]; s2 += r2[i]; }
    float mu  = s * (1.f/Dd);
    float var = s2 * (1.f/Dd) - mu*mu;
    float inv = rsqrtf(var + 1e-5f);
    float4 g  = ((const float4*)gamma)[tid];
    float4 be = ((const float4*)beta)[tid];
    float4 o;
    o.x = (v.x - mu)*inv*g.x + be.x;
    o.y = (v.y - mu)*inv*g.y + be.y;
    o.z = (v.z - mu)*inv*g.z + be.z;
    o.w = (v.w - mu)*inv*g.w + be.w;
    ((float4*)(g_xn + (size_t)row*Dd))[tid] = o;
}

// ---------------- 2. weight prep ------------------------------------------
#define WALL_ELEMS (PSTR*Dd)
#define HW_ELEMS   (QVS*Cc)
__global__ void prep_weights(const float* __restrict__ Wq, const float* __restrict__ Wk,
                             const float* __restrict__ Wv, const float* __restrict__ Wa,
                             const float* __restrict__ Qc, const float* __restrict__ Vc)
{
    int i = blockIdx.x * blockDim.x + threadIdx.x;
    if (i < WALL_ELEMS) {
        int row = i >> 10, col = i & 1023;
        float val;
        if      (row <  64) val = Wq[(size_t)row       *1024 + col];
        else if (row < 128) val = Wk[(size_t)(row- 64) *1024 + col];
        else if (row < 192) val = Wv[(size_t)(row-128) *1024 + col];
        else if (row < 704) val = Wa[(size_t)(row-192) *1024 + col];
        else                val = 0.f;
        g_wall[i] = val;
    } else if (i < WALL_ELEMS + HW_ELEMS) {
        int j = i - WALL_ELEMS;
        int n = j >> 6, c = j & 63;
        if (n < 512) {         // q rows: n = h*64+e
            int h = n >> 6, e = n & 63;
            g_hw[j] = Qc[(size_t)h*Cc*Cc + (size_t)c*Cc + e];
        } else {               // v rows: n-512 = h*128+d
            int nn = n - 512;
            int h = nn >> 7, d = nn & 127;
            g_hw[j] = Vc[(size_t)h*Cc*DVv + (size_t)c*DVv + d];
        }
    }
}

// ---------------- 3. TF32 GEMM, 64x64 warp tile ---------------------------
// Y[M,N] = A[M,K] @ W[N,K]^T. 128 threads, 2x2 warps of 64x64.
// mode 0: plain; 1: += resid; 2: proj epilogue (knorm cols 64-127, sigmoid 192-703)
// mode 3: merged head GEMM (blocks with col0>=512 shift A by +128 to v_lat)
__device__ __forceinline__ uint32_t f2tf32(float f) {
    uint32_t u;
    asm volatile("cvt.rna.tf32.f32 %0, %1;" : "=r"(u) : "f"(f));
    return u;
}
__device__ __forceinline__ void mma_tf32(float c[4], const uint32_t a[4], const uint32_t b[2]) {
    asm volatile(
        "mma.sync.aligned.m16n8k8.row.col.f32.tf32.tf32.f32 "
        "{%0,%1,%2,%3}, {%4,%5,%6,%7}, {%8,%9}, {%0,%1,%2,%3};\n"
        : "+f"(c[0]), "+f"(c[1]), "+f"(c[2]), "+f"(c[3])
        : "r"(a[0]), "r"(a[1]), "r"(a[2]), "r"(a[3]), "r"(b[0]), "r"(b[1]));
}

__global__ __launch_bounds__(128, 2)
void gemm_tf32(int K, int lda, int ldy, int mode,
               const float* __restrict__ A,
               const float* __restrict__ W,
               float* __restrict__ Y,
               const float* __restrict__ resid,
               const float* __restrict__ bias)
{
    __shared__ uint32_t As[2][128*20];
    __shared__ uint32_t Bs[2][128*20];

    int tid  = threadIdx.x;
    int lane = tid & 31, warp = tid >> 5;
    int wm = warp & 1, wn = warp >> 1;       // 2x2 warp grid
    int g  = lane >> 2, tig = lane & 3;
    int row0 = blockIdx.y * 128;
    int col0 = blockIdx.x * 128;
    if (mode == 3 && col0 >= 512) A += 128;  // v_lat slice

    int lrow = tid >> 1;
    int kb   = (tid & 1) * 8;
    const float* Ap = A + (size_t)(row0 + lrow) * lda + kb;
    const float* Bp = W + (size_t)(col0 + lrow) * K + kb;

    float acc[4][8][4];
    #pragma unroll
    for (int i = 0; i < 4; i++)
        #pragma unroll
        for (int j = 0; j < 8; j++)
            #pragma unroll
            for (int e = 0; e < 4; e++) acc[i][j][e] = 0.f;

    {
        float4 a00 = *(const float4*)(Ap);
        float4 a01 = *(const float4*)(Ap + 4);
        float4 a10 = *(const float4*)(Ap + (size_t)64*lda);
        float4 a11 = *(const float4*)(Ap + (size_t)64*lda + 4);
        float4 b00 = *(const float4*)(Bp);
        float4 b01 = *(const float4*)(Bp + 4);
        float4 b10 = *(const float4*)(Bp + (size_t)64*K);
        float4 b11 = *(const float4*)(Bp + (size_t)64*K + 4);
        *(uint4*)&As[0][lrow*20 + kb]          = make_uint4(f2tf32(a00.x), f2tf32(a00.y), f2tf32(a00.z), f2tf32(a00.w));
        *(uint4*)&As[0][lrow*20 + kb + 4]      = make_uint4(f2tf32(a01.x), f2tf32(a01.y), f2tf32(a01.z), f2tf32(a01.w));
        *(uint4*)&As[0][(lrow+64)*20 + kb]     = make_uint4(f2tf32(a10.x), f2tf32(a10.y), f2tf32(a10.z), f2tf32(a10.w));
        *(uint4*)&As[0][(lrow+64)*20 + kb + 4] = make_uint4(f2tf32(a11.x), f2tf32(a11.y), f2tf32(a11.z), f2tf32(a11.w));
        *(uint4*)&Bs[0][lrow*20 + kb]          = make_uint4(f2tf32(b00.x), f2tf32(b00.y), f2tf32(b00.z), f2tf32(b00.w));
        *(uint4*)&Bs[0][lrow*20 + kb + 4]      = make_uint4(f2tf32(b01.x), f2tf32(b01.y), f2tf32(b01.z), f2tf32(b01.w));
        *(uint4*)&Bs[0][(lrow+64)*20 + kb]     = make_uint4(f2tf32(b10.x), f2tf32(b10.y), f2tf32(b10.z), f2tf32(b10.w));
        *(uint4*)&Bs[0][(lrow+64)*20 + kb + 4] = make_uint4(f2tf32(b11.x), f2tf32(b11.y), f2tf32(b11.z), f2tf32(b11.w));
    }
    __syncthreads();

    int buf = 0;
    for (int k0 = 0; k0 < K; k0 += 16) {
        float4 pa00, pa01, pa10, pa11, pb00, pb01, pb10, pb11;
        bool more = (k0 + 16) < K;
        if (more) {
            const float* Ak = Ap + k0 + 16;
            const float* Bk = Bp + k0 + 16;
            pa00 = *(const float4*)(Ak);
            pa01 = *(const float4*)(Ak + 4);
            pa10 = *(const float4*)(Ak + (size_t)64*lda);
            pa11 = *(const float4*)(Ak + (size_t)64*lda + 4);
            pb00 = *(const float4*)(Bk);
            pb01 = *(const float4*)(Bk + 4);
            pb10 = *(const float4*)(Bk + (size_t)64*K);
            pb11 = *(const float4*)(Bk + (size_t)64*K + 4);
        }

        const uint32_t* Ab  = As[buf];
        const uint32_t* Bb_ = Bs[buf];
        #pragma unroll
        for (int ks = 0; ks < 16; ks += 8) {
            uint32_t af[4][4], bf[8][2];
            #pragma unroll
            for (int i = 0; i < 4; i++) {
                int base = (wm*64 + i*16 + g)*20 + ks + tig;
                af[i][0] = Ab[base];
                af[i][1] = Ab[base + 8*20];
                af[i][2] = Ab[base + 4];
                af[i][3] = Ab[base + 8*20 + 4];
            }
            #pragma unroll
            for (int j = 0; j < 8; j++) {
                int base = (wn*64 + j*8 + g)*20 + ks + tig;
                bf[j][0] = Bb_[base];
                bf[j][1] = Bb_[base + 4];
            }
            #pragma unroll
            for (int i = 0; i < 4; i++)
                #pragma unroll
                for (int j = 0; j < 8; j++)
                    mma_tf32(acc[i][j], af[i], bf[j]);
        }

        if (more) {
            int nb = buf ^ 1;
            *(uint4*)&As[nb][lrow*20 + kb]          = make_uint4(f2tf32(pa00.x), f2tf32(pa00.y), f2tf32(pa00.z), f2tf32(pa00.w));
            *(uint4*)&As[nb][lrow*20 + kb + 4]      = make_uint4(f2tf32(pa01.x), f2tf32(pa01.y), f2tf32(pa01.z), f2tf32(pa01.w));
            *(uint4*)&As[nb][(lrow+64)*20 + kb]     = make_uint4(f2tf32(pa10.x), f2tf32(pa10.y), f2tf32(pa10.z), f2tf32(pa10.w));
            *(uint4*)&As[nb][(lrow+64)*20 + kb + 4] = make_uint4(f2tf32(pa11.x), f2tf32(pa11.y), f2tf32(pa11.z), f2tf32(pa11.w));
            *(uint4*)&Bs[nb][lrow*20 + kb]          = make_uint4(f2tf32(pb00.x), f2tf32(pb00.y), f2tf32(pb00.z), f2tf32(pb00.w));
            *(uint4*)&Bs[nb][lrow*20 + kb + 4]      = make_uint4(f2tf32(pb01.x), f2tf32(pb01.y), f2tf32(pb01.z), f2tf32(pb01.w));
            *(uint4*)&Bs[nb][(lrow+64)*20 + kb]     = make_uint4(f2tf32(pb10.x), f2tf32(pb10.y), f2tf32(pb10.z), f2tf32(pb10.w));
            *(uint4*)&Bs[nb][(lrow+64)*20 + kb + 4] = make_uint4(f2tf32(pb11.x), f2tf32(pb11.y), f2tf32(pb11.z), f2tf32(pb11.w));
            __syncthreads();
            buf = nb;
        }
    }

    bool knorm_warp = (mode == 2) && (col0 + wn*64 == 64);
    #pragma unroll
    for (int i = 0; i < 4; i++) {
        #pragma unroll
        for (int half = 0; half < 2; half++) {
            int m = row0 + wm*64 + i*16 + g + half*8;
            float scale = 1.f;
            if (knorm_warp) {
                float s = 0.f;
                #pragma unroll
                for (int j = 0; j < 8; j++) {
                    float e0 = acc[i][j][half*2], e1 = acc[i][j][half*2+1];
                    s = fmaf(e0, e0, s); s = fmaf(e1, e1, s);
                }
                s += __shfl_xor_sync(0xffffffffu, s, 1);
                s += __shfl_xor_sync(0xffffffffu, s, 2);
                scale = 1.f / fmaxf(sqrtf(s), 1e-12f);
            }
            #pragma unroll
            for (int j = 0; j < 8; j++) {
                int n0 = col0 + wn*64 + j*8 + tig*2;
                float2 val = make_float2(acc[i][j][half*2], acc[i][j][half*2+1]);
                if (mode == 1) {
                    const float2 r = *(const float2*)(resid + (size_t)m*ldy + n0);
                    val.x += r.x; val.y += r.y;
                } else if (mode == 2) {
                    if (knorm_warp) {
                        val.x *= scale; val.y *= scale;
                    } else if (n0 >= 192 && n0 < 704) {
                        float2 bb = *(const float2*)(bias + n0 - 192);
                        val.x = 1.f / (1.f + expf(-(val.x + bb.x)));
                        val.y = 1.f / (1.f + expf(-(val.y + bb.y)));
                    }
                }
                *(float2*)(Y + (size_t)m*ldy + n0) = val;
            }
        }
    }
}

// ---------------- 4. recurrent scan (8c x 2v tiles, chunked) ---------------
// Block = (b,h,vhalf). 256 threads: vg = tid>>3 (32 v-pairs), cg = tid&7 (8 c's).
__global__ __launch_bounds__(256)
void scan_kernel()
{
    int blk   = blockIdx.x;
    int bh    = blk >> 1;
    int vhalf = blk & 1;
    int b = bh >> 3, h = bh & 7;
    int tid = threadIdx.x;
    int vg  = tid >> 3;      // 0..31
    int cg  = tid & 7;       // 0..7
    const float* qp = g_qv + (size_t)(b*Tt)*QVS + h*64;
    const float* vp = g_qv + (size_t)(b*Tt)*QVS + 512 + h*128 + vhalf*64;
    const float* pp = g_proj + (size_t)b * Tt * PSTR;
    float* op = g_o + (size_t)b * Tt * Dd + h*DVv + vhalf*64 + vg*2;

    // chunk loader: flat float4 index f = i*256 + tid; q4=f&15, s=(f>>4)&3, r=f>>6
    const float* lsrc[4];
    size_t ladv[4];
    int ldst[4];
    #pragma unroll
    for (int i = 0; i < 4; i++) {
        int f = i * 256 + tid;
        int lq4 = f & 15, ls = (f >> 4) & 3, lr = f >> 6;
        switch (ls) {
            case 0:  lsrc[i] = pp + (size_t)lr*PSTR + 192 + h*64 + lq4*4; ladv[i] = (size_t)CH*PSTR; break;
            case 1:  lsrc[i] = pp + (size_t)lr*PSTR + 64 + lq4*4;         ladv[i] = (size_t)CH*PSTR; break;
            case 2:  lsrc[i] = qp + (size_t)lr*QVS + lq4*4;               ladv[i] = (size_t)CH*QVS;  break;
            default: lsrc[i] = vp + (size_t)lr*QVS + lq4*4;               ladv[i] = (size_t)CH*QVS;  break;
        }
        ldst[i] = (lr*4 + ls)*64 + lq4*4;
    }

    __shared__ __align__(16) float sh[2][CH*256];
    float S0[8], S1[8];
    #pragma unroll
    for (int i = 0; i < 8; i++) { S0[i] = 0.f; S1[i] = 0.f; }

    #pragma unroll
    for (int i = 0; i < 4; i++)
        *(float4*)&sh[0][ldst[i]] = *(const float4*)lsrc[i];
    __syncthreads();

    int buf = 0;
    for (int c = 0; c < Tt/CH; c++) {
        float4 pf[4];
        bool more = (c + 1) < (Tt/CH);
        if (more) {
            #pragma unroll
            for (int i = 0; i < 4; i++)
                pf[i] = *(const float4*)(lsrc[i] + (size_t)(c+1)*ladv[i]);
        }
        const float* cb = sh[buf];
        #pragma unroll 4
        for (int r = 0; r < CH; r++) {
            const float* base = cb + r*256;
            float4 a0 = *(const float4*)(base +       cg*8);
            float4 a1 = *(const float4*)(base +       cg*8 + 4);
            float4 k0 = *(const float4*)(base +  64 + cg*8);
            float4 k1 = *(const float4*)(base +  64 + cg*8 + 4);
            float4 q0 = *(const float4*)(base + 128 + cg*8);
            float4 q1 = *(const float4*)(base + 128 + cg*8 + 4);
            float2 vt = *(const float2*)(base + 192 + vg*2);
            float acc0 = 0.f, acc1 = 0.f;

            S0[0] = fmaf(a0.x, S0[0], k0.x*vt.x); acc0 = fmaf(q0.x, S0[0], acc0);
            S1[0] = fmaf(a0.x, S1[0], k0.x*vt.y); acc1 = fmaf(q0.x, S1[0], acc1);
            S0[1] = fmaf(a0.y, S0[1], k0.y*vt.x); acc0 = fmaf(q0.y, S0[1], acc0);
            S1[1] = fmaf(a0.y, S1[1], k0.y*vt.y); acc1 = fmaf(q0.y, S1[1], acc1);
            S0[2] = fmaf(a0.z, S0[2], k0.z*vt.x); acc0 = fmaf(q0.z, S0[2], acc0);
            S1[2] = fmaf(a0.z, S1[2], k0.z*vt.y); acc1 = fmaf(q0.z, S1[2], acc1);
            S0[3] = fmaf(a0.w, S0[3], k0.w*vt.x); acc0 = fmaf(q0.w, S0[3], acc0);
            S1[3] = fmaf(a0.w, S1[3], k0.w*vt.y); acc1 = fmaf(q0.w, S1[3], acc1);
            S0[4] = fmaf(a1.x, S0[4], k1.x*vt.x); acc0 = fmaf(q1.x, S0[4], acc0);
            S1[4] = fmaf(a1.x, S1[4], k1.x*vt.y); acc1 = fmaf(q1.x, S1[4], acc1);
            S0[5] = fmaf(a1.y, S0[5], k1.y*vt.x); acc0 = fmaf(q1.y, S0[5], acc0);
            S1[5] = fmaf(a1.y, S1[5], k1.y*vt.y); acc1 = fmaf(q1.y, S1[5], acc1);
            S0[6] = fmaf(a1.z, S0[6], k1.z*vt.x); acc0 = fmaf(q1.z, S0[6], acc0);
            S1[6] = fmaf(a1.z, S1[6], k1.z*vt.y); acc1 = fmaf(q1.z, S1[6], acc1);
            S0[7] = fmaf(a1.w, S0[7], k1.w*vt.x); acc0 = fmaf(q1.w, S0[7], acc0);
            S1[7] = fmaf(a1.w, S1[7], k1.w*vt.y); acc1 = fmaf(q1.w, S1[7], acc1);

            acc0 += __shfl_xor_sync(0xffffffffu, acc0, 1);
            acc1 += __shfl_xor_sync(0xffffffffu, acc1, 1);
            acc0 += __shfl_xor_sync(0xffffffffu, acc0, 2);
            acc1 += __shfl_xor_sync(0xffffffffu, acc1, 2);
            acc0 += __shfl_xor_sync(0xffffffffu, acc0, 4);
            acc1 += __shfl_xor_sync(0xffffffffu, acc1, 4);
            if (cg == 0)
                *(float2*)(op + (size_t)(c*CH + r) * Dd) = make_float2(acc0, acc1);
        }
        if (more) {
            int nb = buf ^ 1;
            #pragma unroll
            for (int i = 0; i < 4; i++)
                *(float4*)&sh[nb][ldst[i]] = pf[i];
            __syncthreads();
            buf = nb;
        }
    }
}

// ---------------- launch ---------------------------------------------------
extern "C" void kernel_launch(void* const* d_in, const int* in_sizes, int n_in,
                              void* d_out, int out_size)
{
    const float* x     = (const float*)d_in[0];
    const float* Wq    = (const float*)d_in[1];
    const float* Wk    = (const float*)d_in[2];
    const float* Wv    = (const float*)d_in[3];
    const float* Qc    = (const float*)d_in[4];
    const float* Vc    = (const float*)d_in[5];
    const float* Wa_w  = (const float*)d_in[6];
    const float* Wa_b  = (const float*)d_in[7];
    const float* Wo    = (const float*)d_in[8];
    const float* gamma = (const float*)d_in[9];
    const float* beta  = (const float*)d_in[10];
    float* out = (float*)d_out;

    float *xn, *wall, *hw, *proj, *qv, *o;
    cudaGetSymbolAddress((void**)&xn,   g_xn);
    cudaGetSymbolAddress((void**)&wall, g_wall);
    cudaGetSymbolAddress((void**)&hw,   g_hw);
    cudaGetSymbolAddress((void**)&proj, g_proj);
    cudaGetSymbolAddress((void**)&qv,   g_qv);
    cudaGetSymbolAddress((void**)&o,    g_o);

    int prep_total = WALL_ELEMS + HW_ELEMS;

    // 0: layernorm
    ln_kernel<<<Mm, 256>>>(x, gamma, beta);
    // 1: weight prep
    prep_weights<<<(prep_total + 255)/256, 256>>>(Wq, Wk, Wv, Wa_w, Qc, Vc);
    // 2: dummy (shifts ncu capture slot 3 onto the projection GEMM)
    dummy_k<<<1, 32>>>();
    // 3: projection GEMM + fused epi (knorm + sigmoid)
    gemm_tf32<<<dim3(PSTR/128, Mm/128), 128>>>(Dd, Dd, PSTR, 2, xn, wall, proj, nullptr, Wa_b);
    // 4: merged head GEMM: qv[16384,1536] = [q_lat|v_lat] @ hw^T (K=64)
    gemm_tf32<<<dim3(QVS/128, Mm/128), 128>>>(Cc, PSTR, QVS, 3, proj, hw, qv, nullptr, nullptr);
    // 5: recurrent scan
    scan_kernel<<<128, 256>>>();
    // 6: output GEMM + residual
    gemm_tf32<<<dim3(Dd/128, Mm/128), 128>>>(Dd, Dd, Dd, 1, o, Wo, out, x, nullptr);
}